// round 7
// baseline (speedup 1.0000x reference)
#include <cuda_runtime.h>
#include <cuda_bf16.h>

// RoPE, single fused kernel:
//   blocks [0,64):  build [seq, d/2] cos/sin table (accurate sincosf), publish flag
//   blocks [64,..): issue streaming loads FIRST, spin on flag, rotate, store
// Table build overlaps with wave-1 DRAM loads -> no serialized table kernel.

#define D_MODEL   128
#define D_HALF    64
#define D_VEC4    32            // D_MODEL / 4
#define MAX_SEQ   8192
#define T_BLOCKS  64            // table-builder blocks
#define NTHREADS  256

// {cos,sin} pairs; float4 = two consecutive pairs -> one LDG.128 per thread-pair.
__device__ float4 g_tab4[MAX_SEQ * D_HALF / 2];
__device__ unsigned int g_tab_done = 0;   // table blocks finished (0..T_BLOCKS)
__device__ unsigned int g_fin      = 0;   // all blocks finished (reset logic)

__device__ __forceinline__ float4 rope_rot(float4 v, float4 t) {
    float4 o;
    o.x = fmaf(t.x, v.x, -t.y * v.y);
    o.y = fmaf(t.y, v.x,  t.x * v.y);
    o.z = fmaf(t.z, v.z, -t.w * v.w);
    o.w = fmaf(t.w, v.z,  t.z * v.w);
    return o;
}

// ---------------------------------------------------------------------------
// Fused kernel. q = n4/4 float4s per stream; smask = seq-1 if pow2 else 0.
// ---------------------------------------------------------------------------
__global__ void __launch_bounds__(NTHREADS)
rope_fused(const float4* __restrict__ x, float4* __restrict__ out,
           const void* __restrict__ tok_pos,
           unsigned int seq, unsigned int smask, unsigned int q,
           unsigned int gtotal) {
    const unsigned int bid = blockIdx.x;
    const unsigned int tid = threadIdx.x;

    if (bid < T_BLOCKS) {
        // ---------------- table builder ----------------
        const int* v32 = (const int*)tok_pos;
        bool is64 = false;
        if (seq >= 8)
            is64 = (v32[1] == 0 && v32[3] == 0 && v32[5] == 0 && v32[7] == 0);

        const float LOG2_THETA = 13.287712379549449f; // log2(10000)
        unsigned int total = seq * D_HALF;
        for (unsigned int e = bid * NTHREADS + tid; e < total;
             e += T_BLOCKS * NTHREADS) {
            unsigned int s = e >> 6;            // / D_HALF
            unsigned int i = e & (D_HALF - 1);

            long long p = is64 ? ((const long long*)tok_pos)[s]
                               : (long long)v32[s];

            float ex  = (float)(2u * i) * (1.0f / (float)D_MODEL);
            float inv = exp2f(-ex * LOG2_THETA);
            float ang = (float)p * inv;

            float sn, cs;
            sincosf(ang, &sn, &cs);             // accurate path
            ((float2*)g_tab4)[(size_t)s * D_HALF + i] = make_float2(cs, sn);
        }
        __threadfence();                        // publish table (gpu scope)
        __syncthreads();
        if (tid == 0) atomicAdd(&g_tab_done, 1u);
    } else {
        // ---------------- streaming worker ----------------
        unsigned int i = (bid - T_BLOCKS) * NTHREADS + tid;
        bool active = (i < q);
        unsigned int i0 = i, i1 = i + q, i2 = i + 2u * q, i3 = i + 3u * q;

        float4 v0, v1, v2, v3;
        if (active) {                            // front-batched, in flight
            v0 = __ldcs(x + i0);
            v1 = __ldcs(x + i1);
            v2 = __ldcs(x + i2);
            v3 = __ldcs(x + i3);
        }
        asm volatile("" ::: "memory");           // pin loads before the spin

        if (tid == 0) {
            while (atomicAdd(&g_tab_done, 0u) < T_BLOCKS) __nanosleep(64);
        }
        __syncthreads();                         // broadcast "table ready"

        if (active) {
            unsigned int r0 = i0 >> 5, r1 = i1 >> 5, r2 = i2 >> 5, r3 = i3 >> 5;
            unsigned int s0, s1, s2, s3;
            if (smask) { s0 = r0 & smask; s1 = r1 & smask;
                         s2 = r2 & smask; s3 = r3 & smask; }
            else       { s0 = r0 % seq;   s1 = r1 % seq;
                         s2 = r2 % seq;   s3 = r3 % seq;   }

            float4 t0 = g_tab4[s0 * D_VEC4 + (i0 & (D_VEC4 - 1))];
            float4 t1 = g_tab4[s1 * D_VEC4 + (i1 & (D_VEC4 - 1))];
            float4 t2 = g_tab4[s2 * D_VEC4 + (i2 & (D_VEC4 - 1))];
            float4 t3 = g_tab4[s3 * D_VEC4 + (i3 & (D_VEC4 - 1))];

            __stcs(out + i0, rope_rot(v0, t0));
            __stcs(out + i1, rope_rot(v1, t1));
            __stcs(out + i2, rope_rot(v2, t2));
            __stcs(out + i3, rope_rot(v3, t3));
        }
    }

    // ---------------- per-launch reset (last block out) ----------------
    __syncthreads();
    if (tid == 0) {
        unsigned int f = atomicAdd(&g_fin, 1u);
        if (f == gtotal - 1u) {                  // everyone passed their spin
            *((volatile unsigned int*)&g_tab_done) = 0u;
            __threadfence();
            *((volatile unsigned int*)&g_fin) = 0u;
        }
    }
}

// Tail (n4 % 4 leftovers) — runs after fused kernel, table already built.
__global__ void __launch_bounds__(NTHREADS)
rope_apply1(const float4* __restrict__ x, float4* __restrict__ out,
            unsigned int seq, unsigned int smask,
            unsigned int start, unsigned int n4) {
    unsigned int i = start + blockIdx.x * blockDim.x + threadIdx.x;
    if (i >= n4) return;
    unsigned int r = i >> 5;
    unsigned int s = smask ? (r & smask) : (r % seq);
    float4 v = __ldcs(x + i);
    float4 t = g_tab4[s * D_VEC4 + (i & (D_VEC4 - 1))];
    __stcs(out + i, rope_rot(v, t));
}

// ---------------------------------------------------------------------------
extern "C" void kernel_launch(void* const* d_in, const int* in_sizes, int n_in,
                              void* d_out, int out_size) {
    const float* x  = (const float*)d_in[0];
    const void*  tp = d_in[1];

    unsigned int n_elem = (unsigned int)in_sizes[0];
    unsigned int seq = (unsigned int)in_sizes[1];
    if (seq > MAX_SEQ) seq = MAX_SEQ;
    unsigned int smask = ((seq & (seq - 1)) == 0) ? (seq - 1) : 0u;

    unsigned int n4 = n_elem / 4;
    unsigned int q  = n4 / 4;                    // float4s per stream

    unsigned int wblocks = (q + NTHREADS - 1) / NTHREADS;
    unsigned int gtotal  = T_BLOCKS + wblocks;

    rope_fused<<<gtotal, NTHREADS>>>((const float4*)x, (float4*)d_out, tp,
                                     seq, smask, q, gtotal);

    unsigned int done = q * 4u;
    if (done < n4) {
        unsigned int rem = n4 - done;
        unsigned int blocks = (rem + NTHREADS - 1) / NTHREADS;
        rope_apply1<<<blocks, NTHREADS>>>((const float4*)x, (float4*)d_out,
                                          seq, smask, done, n4);
    }
}

// round 8
// speedup vs baseline: 1.0468x; 1.0468x over previous
#include <cuda_runtime.h>
#include <cuda_bf16.h>

// RoPE, single kernel, no table:
//   x is [BH, seq, 128]. Angles depend only on (s, dim-pair), so a block
//   shaped (TILE_S=8 s-rows x 32 float4-cols) iterating over bh has
//   loop-invariant cos/sin: 2 accurate sincosf per thread into registers,
//   then a pure streaming load/rotate/store loop (16 float4s per thread).
//   Compute is fully hidden under DRAM traffic; no table kernel, no gap.

#define D_MODEL   128
#define D_VEC4    32            // D_MODEL/4
#define TILE_S    8             // s-rows per block
#define BH_CHUNK  16            // bh values per block
#define NTHREADS  256           // TILE_S * D_VEC4
#define MAX_SEQ   8192

__device__ __forceinline__ float4 rope_rot(float4 v, float4 t) {
    float4 o;
    o.x = fmaf(t.x, v.x, -t.y * v.y);
    o.y = fmaf(t.y, v.x,  t.x * v.y);
    o.z = fmaf(t.z, v.z, -t.w * v.w);
    o.w = fmaf(t.w, v.z,  t.z * v.w);
    return o;
}

// token_positions may be serialized int64 or int32. Little-endian int64
// arrays of small positives have zero odd int32 words. The probe LDGs are
// uniform across all threads (L1/L2-hot after the first warp).
__device__ __forceinline__ bool detect_is64(const void* tok, unsigned int seq) {
    if (seq < 8) return false;
    const int* v32 = (const int*)tok;
    return (__ldg(v32 + 1) == 0 && __ldg(v32 + 3) == 0 &&
            __ldg(v32 + 5) == 0 && __ldg(v32 + 7) == 0);
}

__device__ __forceinline__ long long load_pos(const void* tok, unsigned int s,
                                              bool is64) {
    return is64 ? ((const long long*)tok)[s] : (long long)((const int*)tok)[s];
}

// ---------------------------------------------------------------------------
// Fast path: d=128, seq % TILE_S == 0, bh % BH_CHUNK == 0.
// grid = (seq/TILE_S) * (bh/BH_CHUNK)
// ---------------------------------------------------------------------------
__global__ void __launch_bounds__(NTHREADS)
rope_direct(const float4* __restrict__ x, float4* __restrict__ out,
            const void* __restrict__ tok_pos,
            unsigned int seq, unsigned int sb_count) {
    unsigned int sblk  = blockIdx.x % sb_count;
    unsigned int chunk = blockIdx.x / sb_count;
    unsigned int srow  = threadIdx.x >> 5;       // 0..7
    unsigned int d4    = threadIdx.x & 31;       // 0..31
    unsigned int s     = sblk * TILE_S + srow;

    // ---- loop-invariant cos/sin for pairs i0=2*d4, i1=2*d4+1 ----
    const float LOG2_THETA = 13.287712379549449f; // log2(10000)
    bool is64 = detect_is64(tok_pos, seq);
    float pf = (float)load_pos(tok_pos, s, is64);

    float e0 = (float)(4u * d4)      * (1.0f / 128.0f);  // 2*(2*d4)/d
    float e1 = (float)(4u * d4 + 2u) * (1.0f / 128.0f);  // 2*(2*d4+1)/d
    float ang0 = pf * exp2f(-e0 * LOG2_THETA);
    float ang1 = pf * exp2f(-e1 * LOG2_THETA);

    float4 t;
    sincosf(ang0, &t.y, &t.x);   // t.x=cos0, t.y=sin0  (accurate path)
    sincosf(ang1, &t.w, &t.z);   // t.z=cos1, t.w=sin1

    // ---- streaming loop over bh (addresses in float4 units, fits 32-bit) --
    unsigned int stride = seq * D_VEC4;
    unsigned int idx = (chunk * BH_CHUNK * seq + s) * D_VEC4 + d4;

#pragma unroll
    for (int j = 0; j < BH_CHUNK; j += 4) {
        unsigned int i0 = idx;
        unsigned int i1 = idx + stride;
        unsigned int i2 = idx + 2u * stride;
        unsigned int i3 = idx + 3u * stride;
        float4 v0 = __ldcs(x + i0);
        float4 v1 = __ldcs(x + i1);
        float4 v2 = __ldcs(x + i2);
        float4 v3 = __ldcs(x + i3);
        __stcs(out + i0, rope_rot(v0, t));
        __stcs(out + i1, rope_rot(v1, t));
        __stcs(out + i2, rope_rot(v2, t));
        __stcs(out + i3, rope_rot(v3, t));
        idx += 4u * stride;
    }
}

// ---------------------------------------------------------------------------
// Fallback (generic shapes): table + streaming, as in the R5 kernel.
// ---------------------------------------------------------------------------
__device__ float4 g_tab4[MAX_SEQ * (D_MODEL / 2) / 2];

__global__ void rope_build_table(const void* __restrict__ tok_pos, int seq) {
    int idx = blockIdx.x * blockDim.x + threadIdx.x;
    if (idx >= seq * (D_MODEL / 2)) return;
    int s = idx >> 6;
    int i = idx & (D_MODEL / 2 - 1);
    bool is64 = detect_is64(tok_pos, (unsigned)seq);
    long long p = load_pos(tok_pos, (unsigned)s, is64);
    const float LOG2_THETA = 13.287712379549449f;
    float e   = (float)(2 * i) * (1.0f / (float)D_MODEL);
    float ang = (float)p * exp2f(-e * LOG2_THETA);
    float sn, cs;
    sincosf(ang, &sn, &cs);
    ((float2*)g_tab4)[(size_t)s * (D_MODEL / 2) + i] = make_float2(cs, sn);
}

__global__ void __launch_bounds__(NTHREADS)
rope_apply1(const float4* __restrict__ x, float4* __restrict__ out,
            unsigned int seq, unsigned int n4) {
    unsigned int i = blockIdx.x * blockDim.x + threadIdx.x;
    if (i >= n4) return;
    unsigned int r = i >> 5;
    unsigned int s = r % seq;
    float4 v = __ldcs(x + i);
    float4 t = g_tab4[s * D_VEC4 + (i & (D_VEC4 - 1))];
    __stcs(out + i, rope_rot(v, t));
}

// ---------------------------------------------------------------------------
extern "C" void kernel_launch(void* const* d_in, const int* in_sizes, int n_in,
                              void* d_out, int out_size) {
    const float* x  = (const float*)d_in[0];
    const void*  tp = d_in[1];

    unsigned int n_elem = (unsigned int)in_sizes[0];
    unsigned int seq    = (unsigned int)in_sizes[1];

    unsigned int bh = 0;
    bool fast = false;
    if (seq > 0 && n_elem % (seq * D_MODEL) == 0) {
        bh = n_elem / (seq * D_MODEL);
        fast = (seq % TILE_S == 0) && (bh % BH_CHUNK == 0);
    }

    if (fast) {
        unsigned int sb_count = seq / TILE_S;
        unsigned int grid = sb_count * (bh / BH_CHUNK);
        rope_direct<<<grid, NTHREADS>>>((const float4*)x, (float4*)d_out, tp,
                                        seq, sb_count);
    } else {
        unsigned int su = seq > MAX_SEQ ? MAX_SEQ : seq;
        int total = (int)(su * (D_MODEL / 2));
        rope_build_table<<<(total + 255) / 256, 256>>>(tp, (int)su);
        unsigned int n4 = n_elem / 4;
        rope_apply1<<<(n4 + NTHREADS - 1) / NTHREADS, NTHREADS>>>(
            (const float4*)x, (float4*)d_out, su, n4);
    }
}

// round 9
// speedup vs baseline: 1.0745x; 1.0265x over previous
#include <cuda_runtime.h>
#include <cuda_bf16.h>

// RoPE, single launch, table-free.
// x is [BH, seq, 128]. Block = (TILE_S=8 s-rows x 32 float4-cols), covering
// BH_CHUNK=4 bh slices -> grid 16384 blocks for the bench shape (the exact
// block count / memory pattern of the best-measured 74.2us kernel).
// Each thread: issue its 4 streaming loads FIRST (2MB-strided coalesced
// streams), compute its loop-invariant cos/sin quadruple (2 accurate sincosf)
// under the load latency, rotate, store. No table, no second kernel, no gap.

#define D_MODEL   128
#define D_VEC4    32            // D_MODEL/4
#define TILE_S    8             // s-rows per block
#define BH_CHUNK  4             // bh slices per block
#define NTHREADS  256           // TILE_S * D_VEC4
#define MAX_SEQ   8192

__device__ __forceinline__ float4 rope_rot(float4 v, float4 t) {
    float4 o;
    o.x = fmaf(t.x, v.x, -t.y * v.y);
    o.y = fmaf(t.y, v.x,  t.x * v.y);
    o.z = fmaf(t.z, v.z, -t.w * v.w);
    o.w = fmaf(t.w, v.z,  t.z * v.w);
    return o;
}

// token_positions may be serialized int64 or int32. Little-endian int64
// arrays of small positives have zero odd int32 words. Probe words are
// L1/L2-hot after the first warp touches them.
__device__ __forceinline__ bool detect_is64(const void* tok, unsigned int seq) {
    if (seq < 8) return false;
    const int* v32 = (const int*)tok;
    return (__ldg(v32 + 1) == 0 && __ldg(v32 + 3) == 0 &&
            __ldg(v32 + 5) == 0 && __ldg(v32 + 7) == 0);
}

__device__ __forceinline__ long long load_pos(const void* tok, unsigned int s,
                                              bool is64) {
    return is64 ? ((const long long*)tok)[s] : (long long)((const int*)tok)[s];
}

// ---------------------------------------------------------------------------
// Fast path: d=128, seq % TILE_S == 0, bh % BH_CHUNK == 0.
// grid = (bh/BH_CHUNK) * (seq/TILE_S); consecutive blocks sweep s first
// (contiguous addresses within a bh-group slab).
// ---------------------------------------------------------------------------
__global__ void __launch_bounds__(NTHREADS)
rope_direct(const float4* __restrict__ x, float4* __restrict__ out,
            const void* __restrict__ tok_pos,
            unsigned int seq, unsigned int sb_count) {
    unsigned int sblk  = blockIdx.x % sb_count;
    unsigned int chunk = blockIdx.x / sb_count;
    unsigned int srow  = threadIdx.x >> 5;       // 0..7
    unsigned int d4    = threadIdx.x & 31;       // 0..31
    unsigned int s     = sblk * TILE_S + srow;

    // ---- issue the 4 streaming loads immediately (2MB-apart streams) ----
    unsigned int stride = seq * D_VEC4;                       // float4s per bh
    unsigned int base   = (chunk * BH_CHUNK * seq + s) * D_VEC4 + d4;
    unsigned int i0 = base, i1 = base + stride,
                 i2 = base + 2u * stride, i3 = base + 3u * stride;

    float4 v0 = __ldcs(x + i0);
    float4 v1 = __ldcs(x + i1);
    float4 v2 = __ldcs(x + i2);
    float4 v3 = __ldcs(x + i3);

    // ---- cos/sin for pairs 2*d4, 2*d4+1 — computed under load latency ----
    const float LOG2_THETA = 13.287712379549449f; // log2(10000)
    bool is64 = detect_is64(tok_pos, seq);
    float pf = (float)load_pos(tok_pos, s, is64);

    float e0 = (float)(4u * d4)      * (1.0f / 128.0f);  // 2*(2*d4)/d
    float e1 = (float)(4u * d4 + 2u) * (1.0f / 128.0f);  // 2*(2*d4+1)/d
    float ang0 = pf * exp2f(-e0 * LOG2_THETA);
    float ang1 = pf * exp2f(-e1 * LOG2_THETA);

    float4 t;
    sincosf(ang0, &t.y, &t.x);   // t.x=cos0, t.y=sin0  (accurate path)
    sincosf(ang1, &t.w, &t.z);   // t.z=cos1, t.w=sin1

    // ---- rotate + store ----
    __stcs(out + i0, rope_rot(v0, t));
    __stcs(out + i1, rope_rot(v1, t));
    __stcs(out + i2, rope_rot(v2, t));
    __stcs(out + i3, rope_rot(v3, t));
}

// ---------------------------------------------------------------------------
// Fallback (generic shapes): table + streaming kernels.
// ---------------------------------------------------------------------------
__device__ float4 g_tab4[MAX_SEQ * (D_MODEL / 2) / 2];

__global__ void rope_build_table(const void* __restrict__ tok_pos, int seq) {
    int idx = blockIdx.x * blockDim.x + threadIdx.x;
    if (idx >= seq * (D_MODEL / 2)) return;
    int s = idx >> 6;
    int i = idx & (D_MODEL / 2 - 1);
    bool is64 = detect_is64(tok_pos, (unsigned)seq);
    long long p = load_pos(tok_pos, (unsigned)s, is64);
    const float LOG2_THETA = 13.287712379549449f;
    float e   = (float)(2 * i) * (1.0f / (float)D_MODEL);
    float ang = (float)p * exp2f(-e * LOG2_THETA);
    float sn, cs;
    sincosf(ang, &sn, &cs);
    ((float2*)g_tab4)[(size_t)s * (D_MODEL / 2) + i] = make_float2(cs, sn);
}

__global__ void __launch_bounds__(NTHREADS)
rope_apply1(const float4* __restrict__ x, float4* __restrict__ out,
            unsigned int seq, unsigned int n4) {
    unsigned int i = blockIdx.x * blockDim.x + threadIdx.x;
    if (i >= n4) return;
    unsigned int r = i >> 5;
    unsigned int s = r % seq;
    float4 v = __ldcs(x + i);
    float4 t = g_tab4[s * D_VEC4 + (i & (D_VEC4 - 1))];
    __stcs(out + i, rope_rot(v, t));
}

// ---------------------------------------------------------------------------
extern "C" void kernel_launch(void* const* d_in, const int* in_sizes, int n_in,
                              void* d_out, int out_size) {
    const float* x  = (const float*)d_in[0];
    const void*  tp = d_in[1];

    unsigned int n_elem = (unsigned int)in_sizes[0];
    unsigned int seq    = (unsigned int)in_sizes[1];

    unsigned int bh = 0;
    bool fast = false;
    if (seq > 0 && n_elem % (seq * D_MODEL) == 0) {
        bh = n_elem / (seq * D_MODEL);
        fast = (seq % TILE_S == 0) && (bh % BH_CHUNK == 0);
    }

    if (fast) {
        unsigned int sb_count = seq / TILE_S;
        unsigned int grid = sb_count * (bh / BH_CHUNK);
        rope_direct<<<grid, NTHREADS>>>((const float4*)x, (float4*)d_out, tp,
                                        seq, sb_count);
    } else {
        unsigned int su = seq > MAX_SEQ ? MAX_SEQ : seq;
        int total = (int)(su * (D_MODEL / 2));
        rope_build_table<<<(total + 255) / 256, 256>>>(tp, (int)su);
        unsigned int n4 = n_elem / 4;
        rope_apply1<<<(n4 + NTHREADS - 1) / NTHREADS, NTHREADS>>>(
            (const float4*)x, (float4*)d_out, su, n4);
    }
}